// round 12
// baseline (speedup 1.0000x reference)
#include <cuda_runtime.h>
#include <cuda_bf16.h>
#include <cuda_fp16.h>
#include <cstdint>

// ---------------------------------------------------------------------------
// Problem constants
// ---------------------------------------------------------------------------
#define NB 64
#define NT 512
#define NF 1024
#define NL 128
#define NTOT (NT * NF)          // 524288 = T*F
#define NSEG 32                 // t-segments per batch in K1

// Output layout (flat concat in reference return order)
#define OFF_MU    0
#define OFF_STD   (NB * NL)                 // 8192
#define OFF_ZS    (2 * NB * NL)             // 16384
#define OFF_LOC   (3 * NB * NL)             // 24576
#define OFF_SCALE (3 * NB * NL + NB * NTOT) // 33579008

// ---------------------------------------------------------------------------
// Device scratch (no allocation allowed)
// ---------------------------------------------------------------------------
__device__ float g_hpart[NB * NSEG * NF];   // partial sums
__device__ float g_cntpart[NB * NSEG];      // partial mask counts
__device__ float g_zs[NB * NL];             // zs for decoder

// ---------------------------------------------------------------------------
// Small helpers
// ---------------------------------------------------------------------------
__device__ __forceinline__ float softplus_f(float v) {
    return fmaxf(v, 0.0f) + log1pf(expf(-fabsf(v)));
}

// Threefry-2x32, 20 rounds — exact JAX key schedule
__device__ __forceinline__ void tf2x32(unsigned int k0, unsigned int k1,
                                       unsigned int x0, unsigned int x1,
                                       unsigned int& o0, unsigned int& o1) {
    unsigned int ks2 = k0 ^ k1 ^ 0x1BD11BDAu;
    x0 += k0; x1 += k1;
#define TF_R(r) { x0 += x1; x1 = (x1 << (r)) | (x1 >> (32 - (r))); x1 ^= x0; }
    TF_R(13) TF_R(15) TF_R(26) TF_R(6)
    x0 += k1;  x1 += ks2 + 1u;
    TF_R(17) TF_R(29) TF_R(16) TF_R(24)
    x0 += ks2; x1 += k0 + 2u;
    TF_R(13) TF_R(15) TF_R(26) TF_R(6)
    x0 += k0;  x1 += k1 + 3u;
    TF_R(17) TF_R(29) TF_R(16) TF_R(24)
    x0 += k1;  x1 += ks2 + 4u;
    TF_R(13) TF_R(15) TF_R(26) TF_R(6)
    x0 += ks2; x1 += k0 + 5u;
#undef TF_R
    o0 = x0; o1 = x1;
}

// XLA f32 erf_inv (Giles polynomial)
__device__ __forceinline__ float erfinv_xla(float x) {
    float w = -log1pf(-x * x);
    float p;
    if (w < 5.0f) {
        w = w - 2.5f;
        p = 2.81022636e-08f;
        p = fmaf(p, w, 3.43273939e-07f);
        p = fmaf(p, w, -3.5233877e-06f);
        p = fmaf(p, w, -4.39150654e-06f);
        p = fmaf(p, w, 0.00021858087f);
        p = fmaf(p, w, -0.00125372503f);
        p = fmaf(p, w, -0.00417768164f);
        p = fmaf(p, w, 0.246640727f);
        p = fmaf(p, w, 1.50140941f);
    } else {
        w = sqrtf(w) - 3.0f;
        p = -0.000200214257f;
        p = fmaf(p, w, 0.000100950558f);
        p = fmaf(p, w, 0.00134934322f);
        p = fmaf(p, w, -0.00367342844f);
        p = fmaf(p, w, 0.00573950773f);
        p = fmaf(p, w, -0.0076224613f);
        p = fmaf(p, w, 0.00943887047f);
        p = fmaf(p, w, 1.00167406f);
        p = fmaf(p, w, 2.83297682f);
    }
    return p * x;
}

// ---------------------------------------------------------------------------
// mma.sync / ldmatrix helpers (portable sm_80+ PTX)
// ---------------------------------------------------------------------------
__device__ __forceinline__ uint32_t smem_to_u32(const void* smem_ptr) {
    uint32_t addr;
    asm("{ .reg .u64 tmp; cvta.to.shared.u64 tmp, %1; cvt.u32.u64 %0, tmp; }"
        : "=r"(addr) : "l"(smem_ptr));
    return addr;
}

__device__ __forceinline__ void ldsm_x4(uint32_t* r, uint32_t addr) {
    asm volatile("ldmatrix.sync.aligned.m8n8.x4.shared.b16 {%0,%1,%2,%3}, [%4];"
        : "=r"(r[0]), "=r"(r[1]), "=r"(r[2]), "=r"(r[3]) : "r"(addr));
}

__device__ __forceinline__ void ldsm_x2_trans(uint32_t* r, uint32_t addr) {
    asm volatile("ldmatrix.sync.aligned.m8n8.x2.trans.shared.b16 {%0,%1}, [%2];"
        : "=r"(r[0]), "=r"(r[1]) : "r"(addr));
}

__device__ __forceinline__ void mma_f16(float* d, const uint32_t* a, const uint32_t* b) {
    asm volatile(
        "mma.sync.aligned.m16n8k16.row.col.f32.f16.f16.f32 "
        "{%0,%1,%2,%3}, {%4,%5,%6,%7}, {%8,%9}, {%0,%1,%2,%3};"
        : "+f"(d[0]), "+f"(d[1]), "+f"(d[2]), "+f"(d[3])
        : "r"(a[0]), "r"(a[1]), "r"(a[2]), "r"(a[3]), "r"(b[0]), "r"(b[1]));
}

__device__ __forceinline__ uint32_t pack_h2(float x, float y) {
    __half2 h = __floats2half2_rn(x, y);
    return *(uint32_t*)&h;
}

// ---------------------------------------------------------------------------
// K1: column-sum over t (mask only affects the count).  grid (NB, NSEG).
// NSEG=32 -> 2048 blocks: better wave quantization. Single-row loop (low regs).
// ---------------------------------------------------------------------------
__global__ __launch_bounds__(256, 4) void k1_pool(const float* __restrict__ x) {
    const int b = blockIdx.x;
    const int s = blockIdx.y;
    const int warp = threadIdx.x >> 5;
    const int lane = threadIdx.x & 31;

    __shared__ float hsh[NF];
    __shared__ int cnt_sh;
    for (int i = threadIdx.x; i < NF; i += 256) hsh[i] = 0.0f;
    if (threadIdx.x == 0) cnt_sh = 0;
    __syncthreads();

    float4 acc[8];
#pragma unroll
    for (int j = 0; j < 8; ++j) acc[j] = make_float4(0.f, 0.f, 0.f, 0.f);
    int cnt = 0;

    const float* xb = x + ((long long)b * NT + s * (NT / NSEG)) * NF;
    const int rows = NT / NSEG;  // 16
    for (int r = warp; r < rows; r += 8) {
        const float4* row4 = (const float4*)(xb + (long long)r * NF);
        float sum = 0.0f;
#pragma unroll
        for (int j = 0; j < 8; ++j) {
            const float4 v = row4[lane + 32 * j];
            acc[j].x += v.x; acc[j].y += v.y;
            acc[j].z += v.z; acc[j].w += v.w;
            sum += (v.x + v.y) + (v.z + v.w);
        }
#pragma unroll
        for (int o = 16; o > 0; o >>= 1) sum += __shfl_xor_sync(0xffffffffu, sum, o);
        if (sum != 0.0f) cnt++;
    }

#pragma unroll
    for (int j = 0; j < 8; ++j) {
        const int base = (lane + 32 * j) * 4;
        atomicAdd(&hsh[base + 0], acc[j].x);
        atomicAdd(&hsh[base + 1], acc[j].y);
        atomicAdd(&hsh[base + 2], acc[j].z);
        atomicAdd(&hsh[base + 3], acc[j].w);
    }
    if (lane == 0) atomicAdd(&cnt_sh, cnt);
    __syncthreads();

    const int part = b * NSEG + s;
    for (int i = threadIdx.x; i < NF; i += 256) g_hpart[part * NF + i] = hsh[i];
    if (threadIdx.x == 0) g_cntpart[part] = (float)cnt_sh;
}

// ---------------------------------------------------------------------------
// K2: encoder heads + threefry eps + zs.  grid NB+1, 512 threads.
// Extra block writes scale = softplus(log_scale).
// ---------------------------------------------------------------------------
__global__ __launch_bounds__(512) void k2_encode(
    const float* __restrict__ Wmu, const float* __restrict__ bmu,
    const float* __restrict__ Wstd, const float* __restrict__ bstd,
    const float* __restrict__ actionbias, const int* __restrict__ label,
    const float* __restrict__ log_scale,
    float* __restrict__ out) {
    if (blockIdx.x == NB) {
        for (int f = threadIdx.x; f < NF; f += 512)
            out[OFF_SCALE + f] = softplus_f(log_scale[f]);
        return;
    }
    const int b = blockIdx.x;
    const int l = threadIdx.x & 127;
    const int q = threadIdx.x >> 7;   // 0..3

    __shared__ float hsh[NF];
    __shared__ float red_mu[4][NL];
    __shared__ float red_sp[4][NL];
    __shared__ float inv_denom;

    for (int f = threadIdx.x; f < NF; f += 512) {
        float sum = 0.0f;
#pragma unroll
        for (int p = 0; p < NSEG; ++p) sum += g_hpart[(b * NSEG + p) * NF + f];
        hsh[f] = sum;
    }
    if (threadIdx.x == 0) {
        float c = 0.0f;
#pragma unroll
        for (int p = 0; p < NSEG; ++p) c += g_cntpart[b * NSEG + p];
        inv_denom = 1.0f / fmaxf(c, 1.0f);
    }
    __syncthreads();
    const float inv = inv_denom;
    for (int f = threadIdx.x; f < NF; f += 512) hsh[f] *= inv;
    __syncthreads();

    float mu = 0.0f;
    float sp = 0.0f;
    const int f0 = q * (NF / 4);
#pragma unroll 8
    for (int f = f0; f < f0 + NF / 4; ++f) {
        const float hv = hsh[f];
        mu = fmaf(hv, Wmu[f * NL + l], mu);
        sp = fmaf(hv, Wstd[f * NL + l], sp);
    }
    red_mu[q][l] = mu;
    red_sp[q][l] = sp;
    __syncthreads();

    if (q == 0) {
        mu = ((red_mu[0][l] + red_mu[1][l]) + (red_mu[2][l] + red_mu[3][l])) + bmu[l];
        sp = ((red_sp[0][l] + red_sp[1][l]) + (red_sp[2][l] + red_sp[3][l])) + bstd[l];
        const float stdv = softplus_f(sp);

        unsigned int nk0, nk1;
        tf2x32(0u, 0u, 0u, 1u, nk0, nk1);
        const int idx = b * NL + l;
        unsigned int o0, o1;
        tf2x32(nk0, nk1, 0u, (unsigned int)idx, o0, o1);
        const unsigned int bits = o0 ^ o1;
        const float f01 = __uint_as_float(0x3F800000u | (bits >> 9)) - 1.0f;
        float u = fmaf(f01, 2.0f, -0.99999994f);
        u = fmaxf(u, -0.99999994f);
        const float eps = 1.41421356237309515f * erfinv_xla(u);

        const float zs = mu + stdv * eps + actionbias[label[b] * NL + l];

        out[OFF_MU + idx]  = mu;
        out[OFF_STD + idx] = stdv;
        out[OFF_ZS + idx]  = zs;
        g_zs[idx] = zs;
    }
}

// ---------------------------------------------------------------------------
// K3: decoder GEMM via mma.sync fp16 single-pass (z and W both fp16; f32 acc).
// Legacy HMMA on sm_103 runs ~256 MACs/cyc/SM — halving the MMA count vs the
// 2-pass split is the dominant lever. rel_err ~3e-4, under 1e-3.
// Persistent 444 blocks (3 CTAs/SM). Tile = 64 b x 64 n x K=128.
// Warp grid 2(M) x 4(N): warp = 32 b x 16 n.
//   A = zs fp16 in smem [b][l] (272B rows), ldmatrix.x4 — built once.
//   W tile: register-prefetched LDG.128 -> cvt fp16 -> STS.64 (144B rows),
//   ldmatrix.x2.trans.
// ---------------------------------------------------------------------------
#define K3_GRID  444
#define K3_TILES (NTOT / 64)    // 8192
#define ROWB  272               // zs row stride
#define WROWB 144               // W row stride (64 fp16 + 16B pad)

#define ZS_H  0
#define W_H   (64 * ROWB)                   // 17408
#define K3_SMEM (W_H + 128 * WROWB)         // 35840

__global__ __launch_bounds__(256, 3) void k3_decoder_mma(const float* __restrict__ Wd,
                                                         const float* __restrict__ bdec,
                                                         float* __restrict__ out_loc) {
    extern __shared__ char smem[];
    const uint32_t sb = smem_to_u32(smem);
    const int tid  = threadIdx.x;
    const int wid  = tid >> 5;
    const int lane = tid & 31;
    const int wm   = wid & 1;         // M half (b 0-31 / 32-63)
    const int wn   = wid >> 1;        // n group of 16
    const int tl0  = tid >> 4;        // staging: base l row (0..15)
    const int tn8  = (tid & 15) * 8;  // staging: byte offset

    // --- prologue: zs fp16 into smem [b][l] (built once) ---
    for (int i = tid; i < NB * NL; i += 256) {
        const int b = i >> 7;
        const int l = i & 127;
        *(__half*)(smem + ZS_H + b * ROWB + l * 2) = __float2half_rn(g_zs[i]);
    }

    float4 wv[8];

    // load W tile into registers (8 x LDG.128 per thread)
#define K3_LOAD(tile_) do { \
        const float* _src = Wd + (long long)(tile_) * 64 + (tn8 >> 1); \
        _Pragma("unroll") \
        for (int p = 0; p < 8; ++p) \
            wv[p] = *(const float4*)(_src + (long long)(tl0 + p * 16) * NTOT); \
    } while (0)

    // convert registers -> fp16 smem (STS.64), 4 n per thread-slot
#define K3_STORE() do { \
        _Pragma("unroll") \
        for (int p = 0; p < 8; ++p) { \
            const int l = tl0 + p * 16; \
            const float4 v = wv[p]; \
            uint2 h; \
            h.x = pack_h2(v.x, v.y); \
            h.y = pack_h2(v.z, v.w); \
            *(uint2*)(smem + W_H + l * WROWB + tn8) = h; \
        } \
    } while (0)

    int tile = blockIdx.x;
    K3_LOAD(tile);
    K3_STORE();
    __syncthreads();

    // A fragment base: rows wm*32 + (lane&15), col-halves by lane>>4
    const uint32_t arow = (uint32_t)(wm * 32 + (lane & 15)) * ROWB + (uint32_t)(lane >> 4) * 16;
    // B fragment base: rows (lane&15) of k-dim, n offset = wn*16 fp16
    const uint32_t brow = (uint32_t)(lane & 15) * WROWB + (uint32_t)wn * 32;

    for (; tile < K3_TILES; tile += K3_GRID) {
        const int next = tile + K3_GRID;
        if (next < K3_TILES) K3_LOAD(next);   // in flight under compute

        float acc[2][2][4];
#pragma unroll
        for (int mt = 0; mt < 2; ++mt)
#pragma unroll
            for (int nt = 0; nt < 2; ++nt)
#pragma unroll
                for (int r = 0; r < 4; ++r) acc[mt][nt][r] = 0.0f;

#pragma unroll
        for (int ks = 0; ks < 8; ++ks) {
            uint32_t bh[2][2];
            const uint32_t bb = (uint32_t)(16 * ks) * WROWB + brow;
            ldsm_x2_trans(bh[0], sb + W_H + bb);
            ldsm_x2_trans(bh[1], sb + W_H + bb + 16);
#pragma unroll
            for (int mt = 0; mt < 2; ++mt) {
                uint32_t ah[4];
                const uint32_t aa = (uint32_t)(16 * mt) * ROWB + arow + (uint32_t)(ks * 32);
                ldsm_x4(ah, sb + ZS_H + aa);
#pragma unroll
                for (int nt = 0; nt < 2; ++nt)
                    mma_f16(acc[mt][nt], ah, bh[nt]);
            }
        }

        // epilogue: float2 stores
#pragma unroll
        for (int nt = 0; nt < 2; ++nt) {
            const long long n = (long long)tile * 64 + wn * 16 + nt * 8 + 2 * (lane & 3);
            const float2 bd = *(const float2*)(bdec + n);
#pragma unroll
            for (int mt = 0; mt < 2; ++mt) {
                const int b = wm * 32 + mt * 16 + (lane >> 2);
                float2 v0, v1;
                v0.x = acc[mt][nt][0] + bd.x;  v0.y = acc[mt][nt][1] + bd.y;
                v1.x = acc[mt][nt][2] + bd.x;  v1.y = acc[mt][nt][3] + bd.y;
                *(float2*)(out_loc + (long long)b * NTOT + n)       = v0;
                *(float2*)(out_loc + (long long)(b + 8) * NTOT + n) = v1;
            }
        }

        __syncthreads();                       // everyone done reading W smem
        if (next < K3_TILES) K3_STORE();       // write next tile
        __syncthreads();                       // W smem ready
    }
}

// ---------------------------------------------------------------------------
// Launch
// ---------------------------------------------------------------------------
extern "C" void kernel_launch(void* const* d_in, const int* in_sizes, int n_in,
                              void* d_out, int out_size) {
    const float* x          = (const float*)d_in[0];
    const int*   label      = (const int*)d_in[1];
    const float* actionbias = (const float*)d_in[2];
    const float* W_mu       = (const float*)d_in[3];
    const float* b_mu       = (const float*)d_in[4];
    const float* W_std      = (const float*)d_in[5];
    const float* b_std      = (const float*)d_in[6];
    const float* W_dec      = (const float*)d_in[7];
    const float* b_dec      = (const float*)d_in[8];
    const float* log_scale  = (const float*)d_in[9];
    float* out = (float*)d_out;

    static int smem_set = 0;
    if (!smem_set) {
        cudaFuncSetAttribute(k3_decoder_mma, cudaFuncAttributeMaxDynamicSharedMemorySize,
                             K3_SMEM);
        smem_set = 1;
    }

    dim3 g1(NB, NSEG);
    k1_pool<<<g1, 256>>>(x);
    k2_encode<<<NB + 1, 512>>>(W_mu, b_mu, W_std, b_std, actionbias, label, log_scale, out);
    k3_decoder_mma<<<K3_GRID, 256, K3_SMEM>>>(W_dec, b_dec, out + OFF_LOC);
}

// round 13
// speedup vs baseline: 1.0322x; 1.0322x over previous
#include <cuda_runtime.h>
#include <cuda_bf16.h>
#include <cuda_fp16.h>
#include <cstdint>

// ---------------------------------------------------------------------------
// Problem constants
// ---------------------------------------------------------------------------
#define NB 64
#define NT 512
#define NF 1024
#define NL 128
#define NTOT (NT * NF)          // 524288 = T*F
#define NSEG 16                 // t-segments per batch in K1

// Output layout (flat concat in reference return order)
#define OFF_MU    0
#define OFF_STD   (NB * NL)                 // 8192
#define OFF_ZS    (2 * NB * NL)             // 16384
#define OFF_LOC   (3 * NB * NL)             // 24576
#define OFF_SCALE (3 * NB * NL + NB * NTOT) // 33579008

// ---------------------------------------------------------------------------
// Device scratch (no allocation allowed)
// ---------------------------------------------------------------------------
__device__ float g_hpart[NB * NSEG * NF];   // partial sums
__device__ float g_cntpart[NB * NSEG];      // partial mask counts
__device__ float g_zs[NB * NL];             // zs for decoder

// ---------------------------------------------------------------------------
// Small helpers
// ---------------------------------------------------------------------------
__device__ __forceinline__ float softplus_f(float v) {
    return fmaxf(v, 0.0f) + log1pf(expf(-fabsf(v)));
}

// Threefry-2x32, 20 rounds — exact JAX key schedule
__device__ __forceinline__ void tf2x32(unsigned int k0, unsigned int k1,
                                       unsigned int x0, unsigned int x1,
                                       unsigned int& o0, unsigned int& o1) {
    unsigned int ks2 = k0 ^ k1 ^ 0x1BD11BDAu;
    x0 += k0; x1 += k1;
#define TF_R(r) { x0 += x1; x1 = (x1 << (r)) | (x1 >> (32 - (r))); x1 ^= x0; }
    TF_R(13) TF_R(15) TF_R(26) TF_R(6)
    x0 += k1;  x1 += ks2 + 1u;
    TF_R(17) TF_R(29) TF_R(16) TF_R(24)
    x0 += ks2; x1 += k0 + 2u;
    TF_R(13) TF_R(15) TF_R(26) TF_R(6)
    x0 += k0;  x1 += k1 + 3u;
    TF_R(17) TF_R(29) TF_R(16) TF_R(24)
    x0 += k1;  x1 += ks2 + 4u;
    TF_R(13) TF_R(15) TF_R(26) TF_R(6)
    x0 += ks2; x1 += k0 + 5u;
#undef TF_R
    o0 = x0; o1 = x1;
}

// XLA f32 erf_inv (Giles polynomial)
__device__ __forceinline__ float erfinv_xla(float x) {
    float w = -log1pf(-x * x);
    float p;
    if (w < 5.0f) {
        w = w - 2.5f;
        p = 2.81022636e-08f;
        p = fmaf(p, w, 3.43273939e-07f);
        p = fmaf(p, w, -3.5233877e-06f);
        p = fmaf(p, w, -4.39150654e-06f);
        p = fmaf(p, w, 0.00021858087f);
        p = fmaf(p, w, -0.00125372503f);
        p = fmaf(p, w, -0.00417768164f);
        p = fmaf(p, w, 0.246640727f);
        p = fmaf(p, w, 1.50140941f);
    } else {
        w = sqrtf(w) - 3.0f;
        p = -0.000200214257f;
        p = fmaf(p, w, 0.000100950558f);
        p = fmaf(p, w, 0.00134934322f);
        p = fmaf(p, w, -0.00367342844f);
        p = fmaf(p, w, 0.00573950773f);
        p = fmaf(p, w, -0.0076224613f);
        p = fmaf(p, w, 0.00943887047f);
        p = fmaf(p, w, 1.00167406f);
        p = fmaf(p, w, 2.83297682f);
    }
    return p * x;
}

// ---------------------------------------------------------------------------
// mma.sync / ldmatrix / cp.async helpers (portable sm_80+ PTX)
// ---------------------------------------------------------------------------
__device__ __forceinline__ uint32_t smem_to_u32(const void* smem_ptr) {
    uint32_t addr;
    asm("{ .reg .u64 tmp; cvta.to.shared.u64 tmp, %1; cvt.u32.u64 %0, tmp; }"
        : "=r"(addr) : "l"(smem_ptr));
    return addr;
}

__device__ __forceinline__ void ldsm_x4(uint32_t* r, uint32_t addr) {
    asm volatile("ldmatrix.sync.aligned.m8n8.x4.shared.b16 {%0,%1,%2,%3}, [%4];"
        : "=r"(r[0]), "=r"(r[1]), "=r"(r[2]), "=r"(r[3]) : "r"(addr));
}

__device__ __forceinline__ void ldsm_x2_trans(uint32_t* r, uint32_t addr) {
    asm volatile("ldmatrix.sync.aligned.m8n8.x2.trans.shared.b16 {%0,%1}, [%2];"
        : "=r"(r[0]), "=r"(r[1]) : "r"(addr));
}

__device__ __forceinline__ void mma_f16(float* d, const uint32_t* a, const uint32_t* b) {
    asm volatile(
        "mma.sync.aligned.m16n8k16.row.col.f32.f16.f16.f32 "
        "{%0,%1,%2,%3}, {%4,%5,%6,%7}, {%8,%9}, {%0,%1,%2,%3};"
        : "+f"(d[0]), "+f"(d[1]), "+f"(d[2]), "+f"(d[3])
        : "r"(a[0]), "r"(a[1]), "r"(a[2]), "r"(a[3]), "r"(b[0]), "r"(b[1]));
}

__device__ __forceinline__ uint32_t pack_h2(float x, float y) {
    __half2 h = __floats2half2_rn(x, y);
    return *(uint32_t*)&h;
}

__device__ __forceinline__ void cp_async16(uint32_t dst_smem, const void* src_gmem) {
    asm volatile("cp.async.cg.shared.global [%0], [%1], 16;"
                 :: "r"(dst_smem), "l"(src_gmem));
}
#define CP_COMMIT() asm volatile("cp.async.commit_group;" ::: "memory")
#define CP_WAIT1()  asm volatile("cp.async.wait_group 1;" ::: "memory")

// ---------------------------------------------------------------------------
// K1: column-sum over t (mask only affects the count).  grid (NB, NSEG).
// R10 config — best measured (34.3us): NSEG=16, single-row loop, 4 CTAs/SM.
// ---------------------------------------------------------------------------
__global__ __launch_bounds__(256, 4) void k1_pool(const float* __restrict__ x) {
    const int b = blockIdx.x;
    const int s = blockIdx.y;
    const int warp = threadIdx.x >> 5;
    const int lane = threadIdx.x & 31;

    __shared__ float hsh[NF];
    __shared__ int cnt_sh;
    for (int i = threadIdx.x; i < NF; i += 256) hsh[i] = 0.0f;
    if (threadIdx.x == 0) cnt_sh = 0;
    __syncthreads();

    float4 acc[8];
#pragma unroll
    for (int j = 0; j < 8; ++j) acc[j] = make_float4(0.f, 0.f, 0.f, 0.f);
    int cnt = 0;

    const float* xb = x + ((long long)b * NT + s * (NT / NSEG)) * NF;
    const int rows = NT / NSEG;  // 32
    for (int r = warp; r < rows; r += 8) {
        const float4* row4 = (const float4*)(xb + (long long)r * NF);
        float sum = 0.0f;
#pragma unroll
        for (int j = 0; j < 8; ++j) {
            const float4 v = row4[lane + 32 * j];
            acc[j].x += v.x; acc[j].y += v.y;
            acc[j].z += v.z; acc[j].w += v.w;
            sum += (v.x + v.y) + (v.z + v.w);
        }
#pragma unroll
        for (int o = 16; o > 0; o >>= 1) sum += __shfl_xor_sync(0xffffffffu, sum, o);
        if (sum != 0.0f) cnt++;
    }

#pragma unroll
    for (int j = 0; j < 8; ++j) {
        const int base = (lane + 32 * j) * 4;
        atomicAdd(&hsh[base + 0], acc[j].x);
        atomicAdd(&hsh[base + 1], acc[j].y);
        atomicAdd(&hsh[base + 2], acc[j].z);
        atomicAdd(&hsh[base + 3], acc[j].w);
    }
    if (lane == 0) atomicAdd(&cnt_sh, cnt);
    __syncthreads();

    const int part = b * NSEG + s;
    for (int i = threadIdx.x; i < NF; i += 256) g_hpart[part * NF + i] = hsh[i];
    if (threadIdx.x == 0) g_cntpart[part] = (float)cnt_sh;
}

// ---------------------------------------------------------------------------
// K2: encoder heads + threefry eps + zs.  grid NB+1, 512 threads.
// Extra block writes scale = softplus(log_scale).
// ---------------------------------------------------------------------------
__global__ __launch_bounds__(512) void k2_encode(
    const float* __restrict__ Wmu, const float* __restrict__ bmu,
    const float* __restrict__ Wstd, const float* __restrict__ bstd,
    const float* __restrict__ actionbias, const int* __restrict__ label,
    const float* __restrict__ log_scale,
    float* __restrict__ out) {
    if (blockIdx.x == NB) {
        for (int f = threadIdx.x; f < NF; f += 512)
            out[OFF_SCALE + f] = softplus_f(log_scale[f]);
        return;
    }
    const int b = blockIdx.x;
    const int l = threadIdx.x & 127;
    const int q = threadIdx.x >> 7;   // 0..3

    __shared__ float hsh[NF];
    __shared__ float red_mu[4][NL];
    __shared__ float red_sp[4][NL];
    __shared__ float inv_denom;

    for (int f = threadIdx.x; f < NF; f += 512) {
        float sum = 0.0f;
#pragma unroll
        for (int p = 0; p < NSEG; ++p) sum += g_hpart[(b * NSEG + p) * NF + f];
        hsh[f] = sum;
    }
    if (threadIdx.x == 0) {
        float c = 0.0f;
#pragma unroll
        for (int p = 0; p < NSEG; ++p) c += g_cntpart[b * NSEG + p];
        inv_denom = 1.0f / fmaxf(c, 1.0f);
    }
    __syncthreads();
    const float inv = inv_denom;
    for (int f = threadIdx.x; f < NF; f += 512) hsh[f] *= inv;
    __syncthreads();

    float mu = 0.0f;
    float sp = 0.0f;
    const int f0 = q * (NF / 4);
#pragma unroll 8
    for (int f = f0; f < f0 + NF / 4; ++f) {
        const float hv = hsh[f];
        mu = fmaf(hv, Wmu[f * NL + l], mu);
        sp = fmaf(hv, Wstd[f * NL + l], sp);
    }
    red_mu[q][l] = mu;
    red_sp[q][l] = sp;
    __syncthreads();

    if (q == 0) {
        mu = ((red_mu[0][l] + red_mu[1][l]) + (red_mu[2][l] + red_mu[3][l])) + bmu[l];
        sp = ((red_sp[0][l] + red_sp[1][l]) + (red_sp[2][l] + red_sp[3][l])) + bstd[l];
        const float stdv = softplus_f(sp);

        unsigned int nk0, nk1;
        tf2x32(0u, 0u, 0u, 1u, nk0, nk1);
        const int idx = b * NL + l;
        unsigned int o0, o1;
        tf2x32(nk0, nk1, 0u, (unsigned int)idx, o0, o1);
        const unsigned int bits = o0 ^ o1;
        const float f01 = __uint_as_float(0x3F800000u | (bits >> 9)) - 1.0f;
        float u = fmaf(f01, 2.0f, -0.99999994f);
        u = fmaxf(u, -0.99999994f);
        const float eps = 1.41421356237309515f * erfinv_xla(u);

        const float zs = mu + stdv * eps + actionbias[label[b] * NL + l];

        out[OFF_MU + idx]  = mu;
        out[OFF_STD + idx] = stdv;
        out[OFF_ZS + idx]  = zs;
        g_zs[idx] = zs;
    }
}

// ---------------------------------------------------------------------------
// K3: decoder GEMM, fp16 single-pass mma.sync, cp.async W pipeline.
// DRAM-latency bound before: only ~24 KB in flight/SM. cp.async 2-stage ring
// keeps up to 64 KB/SM outstanding with zero register staging.
// Persistent 296 blocks (2 CTAs/SM). Tile = 64 b x 64 n x K=128.
// Per tile: issue cp.async for tile+1 (f32 ring) -> wait tile -> LDS f32,
// cvt fp16, STS (144B rows) -> ldsm/mma -> coalesced epilogue.
// ---------------------------------------------------------------------------
#define K3_GRID  296
#define K3_TILES (NTOT / 64)    // 8192
#define ROWB  272               // zs fp16 row stride
#define WROWB 144               // W fp16 row stride (64 fp16 + 16B pad)
#define F32ROW 256              // W f32 row stride (64 f32, contiguous)

#define ZS_OFF  0
#define WH_OFF  (64 * ROWB)                      // 17408
#define F32_OFF (WH_OFF + 128 * WROWB)           // 35840
#define F32_STAGE (128 * F32ROW)                 // 32768
#define K3_SMEM (F32_OFF + 2 * F32_STAGE)        // 101376

__global__ __launch_bounds__(256, 2) void k3_decoder_mma(const float* __restrict__ Wd,
                                                         const float* __restrict__ bdec,
                                                         float* __restrict__ out_loc) {
    extern __shared__ char smem[];
    const uint32_t sb = smem_to_u32(smem);
    const int tid  = threadIdx.x;
    const int wid  = tid >> 5;
    const int lane = tid & 31;
    const int wm   = wid & 1;         // M half (b 0-31 / 32-63)
    const int wn   = wid >> 1;        // n group of 16
    const int tl0  = tid >> 4;        // convert: base l row (0..15)
    const int c4   = tid & 15;        // convert: float4 slot within row

    // --- prologue: zs fp16 into smem [b][l] (built once) ---
    for (int i = tid; i < NB * NL; i += 256) {
        const int b = i >> 7;
        const int l = i & 127;
        *(__half*)(smem + ZS_OFF + b * ROWB + l * 2) = __float2half_rn(g_zs[i]);
    }

    // issue cp.async for one W tile (128 rows x 256B) into ring stage s
#define K3_ISSUE(tile_, s_) do { \
        const uint32_t _dst = sb + F32_OFF + (s_) * F32_STAGE; \
        const float* _src = Wd + (long long)(tile_) * 64; \
        _Pragma("unroll") \
        for (int k = 0; k < 8; ++k) { \
            const int _idx = tid + k * 256; \
            const int _row = _idx >> 4; \
            const int _c   = _idx & 15; \
            cp_async16(_dst + _row * F32ROW + _c * 16, \
                       _src + (long long)_row * NTOT + _c * 4); \
        } \
    } while (0)

    // convert ring stage s (f32) -> fp16 W buffer
#define K3_CONVERT(s_) do { \
        const char* _f32 = smem + F32_OFF + (s_) * F32_STAGE; \
        _Pragma("unroll") \
        for (int p = 0; p < 8; ++p) { \
            const int l = tl0 + p * 16; \
            const float4 v = *(const float4*)(_f32 + l * F32ROW + c4 * 16); \
            uint2 h; \
            h.x = pack_h2(v.x, v.y); \
            h.y = pack_h2(v.z, v.w); \
            *(uint2*)(smem + WH_OFF + l * WROWB + c4 * 8) = h; \
        } \
    } while (0)

    int tile = blockIdx.x;
    K3_ISSUE(tile, 0);
    CP_COMMIT();
    int stage = 0;

    // A fragment base: rows wm*32 + (lane&15), col-halves by lane>>4
    const uint32_t arow = (uint32_t)(wm * 32 + (lane & 15)) * ROWB + (uint32_t)(lane >> 4) * 16;
    // B fragment base: rows (lane&15) of k-dim, n offset = wn*16 fp16
    const uint32_t brow = (uint32_t)(lane & 15) * WROWB + (uint32_t)wn * 32;

    for (; tile < K3_TILES; tile += K3_GRID) {
        const int next = tile + K3_GRID;
        if (next < K3_TILES) K3_ISSUE(next, stage ^ 1);
        CP_COMMIT();
        CP_WAIT1();            // current tile's stage resident
        __syncthreads();       // also orders prior mma reads vs convert writes

        K3_CONVERT(stage);
        __syncthreads();

        float acc[2][2][4];
#pragma unroll
        for (int mt = 0; mt < 2; ++mt)
#pragma unroll
            for (int nt = 0; nt < 2; ++nt)
#pragma unroll
                for (int r = 0; r < 4; ++r) acc[mt][nt][r] = 0.0f;

#pragma unroll
        for (int ks = 0; ks < 8; ++ks) {
            uint32_t bh[2][2];
            const uint32_t bb = (uint32_t)(16 * ks) * WROWB + brow;
            ldsm_x2_trans(bh[0], sb + WH_OFF + bb);
            ldsm_x2_trans(bh[1], sb + WH_OFF + bb + 16);
#pragma unroll
            for (int mt = 0; mt < 2; ++mt) {
                uint32_t ah[4];
                const uint32_t aa = (uint32_t)(16 * mt) * ROWB + arow + (uint32_t)(ks * 32);
                ldsm_x4(ah, sb + ZS_OFF + aa);
#pragma unroll
                for (int nt = 0; nt < 2; ++nt)
                    mma_f16(acc[mt][nt], ah, bh[nt]);
            }
        }

        // epilogue: float2 stores
#pragma unroll
        for (int nt = 0; nt < 2; ++nt) {
            const long long n = (long long)tile * 64 + wn * 16 + nt * 8 + 2 * (lane & 3);
            const float2 bd = *(const float2*)(bdec + n);
#pragma unroll
            for (int mt = 0; mt < 2; ++mt) {
                const int b = wm * 32 + mt * 16 + (lane >> 2);
                float2 v0, v1;
                v0.x = acc[mt][nt][0] + bd.x;  v0.y = acc[mt][nt][1] + bd.y;
                v1.x = acc[mt][nt][2] + bd.x;  v1.y = acc[mt][nt][3] + bd.y;
                *(float2*)(out_loc + (long long)b * NTOT + n)       = v0;
                *(float2*)(out_loc + (long long)(b + 8) * NTOT + n) = v1;
            }
        }

        stage ^= 1;
    }
}

// ---------------------------------------------------------------------------
// Launch
// ---------------------------------------------------------------------------
extern "C" void kernel_launch(void* const* d_in, const int* in_sizes, int n_in,
                              void* d_out, int out_size) {
    const float* x          = (const float*)d_in[0];
    const int*   label      = (const int*)d_in[1];
    const float* actionbias = (const float*)d_in[2];
    const float* W_mu       = (const float*)d_in[3];
    const float* b_mu       = (const float*)d_in[4];
    const float* W_std      = (const float*)d_in[5];
    const float* b_std      = (const float*)d_in[6];
    const float* W_dec      = (const float*)d_in[7];
    const float* b_dec      = (const float*)d_in[8];
    const float* log_scale  = (const float*)d_in[9];
    float* out = (float*)d_out;

    static int smem_set = 0;
    if (!smem_set) {
        cudaFuncSetAttribute(k3_decoder_mma, cudaFuncAttributeMaxDynamicSharedMemorySize,
                             K3_SMEM);
        smem_set = 1;
    }

    dim3 g1(NB, NSEG);
    k1_pool<<<g1, 256>>>(x);
    k2_encode<<<NB + 1, 512>>>(W_mu, b_mu, W_std, b_std, actionbias, label, log_scale, out);
    k3_decoder_mma<<<K3_GRID, 256, K3_SMEM>>>(W_dec, b_dec, out + OFF_LOC);
}

// round 14
// speedup vs baseline: 1.0448x; 1.0121x over previous
#include <cuda_runtime.h>
#include <cuda_bf16.h>
#include <cuda_fp16.h>
#include <cstdint>

// ---------------------------------------------------------------------------
// Problem constants
// ---------------------------------------------------------------------------
#define NB 64
#define NT 512
#define NF 1024
#define NL 128
#define NTOT (NT * NF)          // 524288 = T*F
#define NSEG 16                 // t-segments per batch in K1

// Output layout (flat concat in reference return order)
#define OFF_MU    0
#define OFF_STD   (NB * NL)                 // 8192
#define OFF_ZS    (2 * NB * NL)             // 16384
#define OFF_LOC   (3 * NB * NL)             // 24576
#define OFF_SCALE (3 * NB * NL + NB * NTOT) // 33579008

// ---------------------------------------------------------------------------
// Device scratch (no allocation allowed)
// ---------------------------------------------------------------------------
__device__ float g_hpart[NB * NSEG * NF];   // partial sums
__device__ float g_cntpart[NB * NSEG];      // partial mask counts
__device__ float g_zs[NB * NL];             // zs for decoder

// ---------------------------------------------------------------------------
// Small helpers
// ---------------------------------------------------------------------------
__device__ __forceinline__ float softplus_f(float v) {
    return fmaxf(v, 0.0f) + log1pf(expf(-fabsf(v)));
}

// Threefry-2x32, 20 rounds — exact JAX key schedule
__device__ __forceinline__ void tf2x32(unsigned int k0, unsigned int k1,
                                       unsigned int x0, unsigned int x1,
                                       unsigned int& o0, unsigned int& o1) {
    unsigned int ks2 = k0 ^ k1 ^ 0x1BD11BDAu;
    x0 += k0; x1 += k1;
#define TF_R(r) { x0 += x1; x1 = (x1 << (r)) | (x1 >> (32 - (r))); x1 ^= x0; }
    TF_R(13) TF_R(15) TF_R(26) TF_R(6)
    x0 += k1;  x1 += ks2 + 1u;
    TF_R(17) TF_R(29) TF_R(16) TF_R(24)
    x0 += ks2; x1 += k0 + 2u;
    TF_R(13) TF_R(15) TF_R(26) TF_R(6)
    x0 += k0;  x1 += k1 + 3u;
    TF_R(17) TF_R(29) TF_R(16) TF_R(24)
    x0 += k1;  x1 += ks2 + 4u;
    TF_R(13) TF_R(15) TF_R(26) TF_R(6)
    x0 += ks2; x1 += k0 + 5u;
#undef TF_R
    o0 = x0; o1 = x1;
}

// XLA f32 erf_inv (Giles polynomial)
__device__ __forceinline__ float erfinv_xla(float x) {
    float w = -log1pf(-x * x);
    float p;
    if (w < 5.0f) {
        w = w - 2.5f;
        p = 2.81022636e-08f;
        p = fmaf(p, w, 3.43273939e-07f);
        p = fmaf(p, w, -3.5233877e-06f);
        p = fmaf(p, w, -4.39150654e-06f);
        p = fmaf(p, w, 0.00021858087f);
        p = fmaf(p, w, -0.00125372503f);
        p = fmaf(p, w, -0.00417768164f);
        p = fmaf(p, w, 0.246640727f);
        p = fmaf(p, w, 1.50140941f);
    } else {
        w = sqrtf(w) - 3.0f;
        p = -0.000200214257f;
        p = fmaf(p, w, 0.000100950558f);
        p = fmaf(p, w, 0.00134934322f);
        p = fmaf(p, w, -0.00367342844f);
        p = fmaf(p, w, 0.00573950773f);
        p = fmaf(p, w, -0.0076224613f);
        p = fmaf(p, w, 0.00943887047f);
        p = fmaf(p, w, 1.00167406f);
        p = fmaf(p, w, 2.83297682f);
    }
    return p * x;
}

// ---------------------------------------------------------------------------
// mma.sync / ldmatrix / cp.async helpers (portable sm_80+ PTX)
// ---------------------------------------------------------------------------
__device__ __forceinline__ uint32_t smem_to_u32(const void* smem_ptr) {
    uint32_t addr;
    asm("{ .reg .u64 tmp; cvta.to.shared.u64 tmp, %1; cvt.u32.u64 %0, tmp; }"
        : "=r"(addr) : "l"(smem_ptr));
    return addr;
}

__device__ __forceinline__ void ldsm_x4(uint32_t* r, uint32_t addr) {
    asm volatile("ldmatrix.sync.aligned.m8n8.x4.shared.b16 {%0,%1,%2,%3}, [%4];"
        : "=r"(r[0]), "=r"(r[1]), "=r"(r[2]), "=r"(r[3]) : "r"(addr));
}

__device__ __forceinline__ void ldsm_x2_trans(uint32_t* r, uint32_t addr) {
    asm volatile("ldmatrix.sync.aligned.m8n8.x2.trans.shared.b16 {%0,%1}, [%2];"
        : "=r"(r[0]), "=r"(r[1]) : "r"(addr));
}

__device__ __forceinline__ void mma_f16(float* d, const uint32_t* a, const uint32_t* b) {
    asm volatile(
        "mma.sync.aligned.m16n8k16.row.col.f32.f16.f16.f32 "
        "{%0,%1,%2,%3}, {%4,%5,%6,%7}, {%8,%9}, {%0,%1,%2,%3};"
        : "+f"(d[0]), "+f"(d[1]), "+f"(d[2]), "+f"(d[3])
        : "r"(a[0]), "r"(a[1]), "r"(a[2]), "r"(a[3]), "r"(b[0]), "r"(b[1]));
}

__device__ __forceinline__ uint32_t pack_h2(float x, float y) {
    __half2 h = __floats2half2_rn(x, y);
    return *(uint32_t*)&h;
}

__device__ __forceinline__ void cp_async16(uint32_t dst_smem, const void* src_gmem) {
    asm volatile("cp.async.cg.shared.global [%0], [%1], 16;"
                 :: "r"(dst_smem), "l"(src_gmem));
}
#define CP_COMMIT() asm volatile("cp.async.commit_group;" ::: "memory")
#define CP_WAIT1()  asm volatile("cp.async.wait_group 1;" ::: "memory")

// ---------------------------------------------------------------------------
// K1: column-sum over t (mask only affects the count).  grid (NB, NSEG).
// Best measured config (34.3-34.7us).
// ---------------------------------------------------------------------------
__global__ __launch_bounds__(256, 4) void k1_pool(const float* __restrict__ x) {
    const int b = blockIdx.x;
    const int s = blockIdx.y;
    const int warp = threadIdx.x >> 5;
    const int lane = threadIdx.x & 31;

    __shared__ float hsh[NF];
    __shared__ int cnt_sh;
    for (int i = threadIdx.x; i < NF; i += 256) hsh[i] = 0.0f;
    if (threadIdx.x == 0) cnt_sh = 0;
    __syncthreads();

    float4 acc[8];
#pragma unroll
    for (int j = 0; j < 8; ++j) acc[j] = make_float4(0.f, 0.f, 0.f, 0.f);
    int cnt = 0;

    const float* xb = x + ((long long)b * NT + s * (NT / NSEG)) * NF;
    const int rows = NT / NSEG;  // 32
    for (int r = warp; r < rows; r += 8) {
        const float4* row4 = (const float4*)(xb + (long long)r * NF);
        float sum = 0.0f;
#pragma unroll
        for (int j = 0; j < 8; ++j) {
            const float4 v = row4[lane + 32 * j];
            acc[j].x += v.x; acc[j].y += v.y;
            acc[j].z += v.z; acc[j].w += v.w;
            sum += (v.x + v.y) + (v.z + v.w);
        }
#pragma unroll
        for (int o = 16; o > 0; o >>= 1) sum += __shfl_xor_sync(0xffffffffu, sum, o);
        if (sum != 0.0f) cnt++;
    }

#pragma unroll
    for (int j = 0; j < 8; ++j) {
        const int base = (lane + 32 * j) * 4;
        atomicAdd(&hsh[base + 0], acc[j].x);
        atomicAdd(&hsh[base + 1], acc[j].y);
        atomicAdd(&hsh[base + 2], acc[j].z);
        atomicAdd(&hsh[base + 3], acc[j].w);
    }
    if (lane == 0) atomicAdd(&cnt_sh, cnt);
    __syncthreads();

    const int part = b * NSEG + s;
    for (int i = threadIdx.x; i < NF; i += 256) g_hpart[part * NF + i] = hsh[i];
    if (threadIdx.x == 0) g_cntpart[part] = (float)cnt_sh;
}

// ---------------------------------------------------------------------------
// K2: encoder heads + threefry eps + zs.  grid NB+1, 512 threads.
// Extra block writes scale = softplus(log_scale).
// ---------------------------------------------------------------------------
__global__ __launch_bounds__(512) void k2_encode(
    const float* __restrict__ Wmu, const float* __restrict__ bmu,
    const float* __restrict__ Wstd, const float* __restrict__ bstd,
    const float* __restrict__ actionbias, const int* __restrict__ label,
    const float* __restrict__ log_scale,
    float* __restrict__ out) {
    if (blockIdx.x == NB) {
        for (int f = threadIdx.x; f < NF; f += 512)
            out[OFF_SCALE + f] = softplus_f(log_scale[f]);
        return;
    }
    const int b = blockIdx.x;
    const int l = threadIdx.x & 127;
    const int q = threadIdx.x >> 7;   // 0..3

    __shared__ float hsh[NF];
    __shared__ float red_mu[4][NL];
    __shared__ float red_sp[4][NL];
    __shared__ float inv_denom;

    for (int f = threadIdx.x; f < NF; f += 512) {
        float sum = 0.0f;
#pragma unroll
        for (int p = 0; p < NSEG; ++p) sum += g_hpart[(b * NSEG + p) * NF + f];
        hsh[f] = sum;
    }
    if (threadIdx.x == 0) {
        float c = 0.0f;
#pragma unroll
        for (int p = 0; p < NSEG; ++p) c += g_cntpart[b * NSEG + p];
        inv_denom = 1.0f / fmaxf(c, 1.0f);
    }
    __syncthreads();
    const float inv = inv_denom;
    for (int f = threadIdx.x; f < NF; f += 512) hsh[f] *= inv;
    __syncthreads();

    float mu = 0.0f;
    float sp = 0.0f;
    const int f0 = q * (NF / 4);
#pragma unroll 8
    for (int f = f0; f < f0 + NF / 4; ++f) {
        const float hv = hsh[f];
        mu = fmaf(hv, Wmu[f * NL + l], mu);
        sp = fmaf(hv, Wstd[f * NL + l], sp);
    }
    red_mu[q][l] = mu;
    red_sp[q][l] = sp;
    __syncthreads();

    if (q == 0) {
        mu = ((red_mu[0][l] + red_mu[1][l]) + (red_mu[2][l] + red_mu[3][l])) + bmu[l];
        sp = ((red_sp[0][l] + red_sp[1][l]) + (red_sp[2][l] + red_sp[3][l])) + bstd[l];
        const float stdv = softplus_f(sp);

        unsigned int nk0, nk1;
        tf2x32(0u, 0u, 0u, 1u, nk0, nk1);
        const int idx = b * NL + l;
        unsigned int o0, o1;
        tf2x32(nk0, nk1, 0u, (unsigned int)idx, o0, o1);
        const unsigned int bits = o0 ^ o1;
        const float f01 = __uint_as_float(0x3F800000u | (bits >> 9)) - 1.0f;
        float u = fmaf(f01, 2.0f, -0.99999994f);
        u = fmaxf(u, -0.99999994f);
        const float eps = 1.41421356237309515f * erfinv_xla(u);

        const float zs = mu + stdv * eps + actionbias[label[b] * NL + l];

        out[OFF_MU + idx]  = mu;
        out[OFF_STD + idx] = stdv;
        out[OFF_ZS + idx]  = zs;
        g_zs[idx] = zs;
    }
}

// ---------------------------------------------------------------------------
// K3: decoder GEMM, fp16 single-pass mma.sync, WIDE-STRIP cp.async pipeline.
// Strip = 64 b x 128 n x K=128: W bursts are 512B per l-row (2x wider than
// before) to improve DRAM row-buffer locality — the hypothesized binder.
// 1 CTA/SM (grid 148), 512 threads (16 warps = 2 b-halves x 8 n-groups).
// 2-stage 64KB f32 cp.async ring; convert -> fp16 buffer -> ldsm/mma.
// ---------------------------------------------------------------------------
#define K3_GRID   148
#define K3_STRIPS (NTOT / 128)   // 4096
#define ROWB   272               // zs fp16 row stride (64 rows)
#define WROWB  272               // W fp16 row stride (128 fp16 = 256B + 16 pad)
#define F32ROW 512               // W f32 row stride (128 f32, contiguous)

#define ZS_OFF  0
#define WH_OFF  (64 * ROWB)                      // 17408
#define F32_OFF (WH_OFF + 128 * WROWB)           // 52224
#define F32_STAGE (128 * F32ROW)                 // 65536
#define K3_SMEM (F32_OFF + 2 * F32_STAGE)        // 183296

__global__ __launch_bounds__(512, 1) void k3_decoder_mma(const float* __restrict__ Wd,
                                                         const float* __restrict__ bdec,
                                                         float* __restrict__ out_loc) {
    extern __shared__ char smem[];
    const uint32_t sb = smem_to_u32(smem);
    const int tid  = threadIdx.x;
    const int wid  = tid >> 5;
    const int lane = tid & 31;
    const int wm   = wid & 1;         // M half (b 0-31 / 32-63)
    const int wn   = wid >> 1;        // n group of 16 (0..7)
    const int tl0  = tid >> 5;        // convert: base l row (0..15)

    // --- prologue: zs fp16 into smem [b][l] (built once) ---
    for (int i = tid; i < NB * NL; i += 512) {
        const int b = i >> 7;
        const int l = i & 127;
        *(__half*)(smem + ZS_OFF + b * ROWB + l * 2) = __float2half_rn(g_zs[i]);
    }

    // issue cp.async for one W strip (128 rows x 512B) into ring stage s
#define K3_ISSUE(strip_, s_) do { \
        const uint32_t _dst = sb + F32_OFF + (s_) * F32_STAGE; \
        const float* _src = Wd + (long long)(strip_) * 128; \
        _Pragma("unroll") \
        for (int k = 0; k < 8; ++k) { \
            const int _idx = tid + k * 512; \
            const int _row = _idx >> 5; \
            const int _c   = _idx & 31; \
            cp_async16(_dst + _row * F32ROW + _c * 16, \
                       _src + (long long)_row * NTOT + _c * 4); \
        } \
    } while (0)

    // convert ring stage s (f32) -> fp16 W buffer; warp = one row (conflict-free)
#define K3_CONVERT(s_) do { \
        const char* _f32 = smem + F32_OFF + (s_) * F32_STAGE; \
        _Pragma("unroll") \
        for (int p = 0; p < 8; ++p) { \
            const int l = tl0 + p * 16; \
            const float4 v = *(const float4*)(_f32 + l * F32ROW + lane * 16); \
            uint2 h; \
            h.x = pack_h2(v.x, v.y); \
            h.y = pack_h2(v.z, v.w); \
            *(uint2*)(smem + WH_OFF + l * WROWB + lane * 8) = h; \
        } \
    } while (0)

    int strip = blockIdx.x;
    K3_ISSUE(strip, 0);
    CP_COMMIT();
    int stage = 0;

    // A fragment base: rows wm*32 + (lane&15), col-halves by lane>>4
    const uint32_t arow = (uint32_t)(wm * 32 + (lane & 15)) * ROWB + (uint32_t)(lane >> 4) * 16;
    // B fragment base: rows (lane&15) of k-dim, n offset = wn*16 fp16 = 32B
    const uint32_t brow = (uint32_t)(lane & 15) * WROWB + (uint32_t)wn * 32;

    for (; strip < K3_STRIPS; strip += K3_GRID) {
        const int next = strip + K3_GRID;
        if (next < K3_STRIPS) K3_ISSUE(next, stage ^ 1);
        CP_COMMIT();
        CP_WAIT1();            // current strip's stage resident
        __syncthreads();       // orders prior mma reads vs convert writes

        K3_CONVERT(stage);
        __syncthreads();

        float acc[2][2][4];
#pragma unroll
        for (int mt = 0; mt < 2; ++mt)
#pragma unroll
            for (int nt = 0; nt < 2; ++nt)
#pragma unroll
                for (int r = 0; r < 4; ++r) acc[mt][nt][r] = 0.0f;

#pragma unroll
        for (int ks = 0; ks < 8; ++ks) {
            uint32_t bh[2][2];
            const uint32_t bb = (uint32_t)(16 * ks) * WROWB + brow;
            ldsm_x2_trans(bh[0], sb + WH_OFF + bb);
            ldsm_x2_trans(bh[1], sb + WH_OFF + bb + 16);
#pragma unroll
            for (int mt = 0; mt < 2; ++mt) {
                uint32_t ah[4];
                const uint32_t aa = (uint32_t)(16 * mt) * ROWB + arow + (uint32_t)(ks * 32);
                ldsm_x4(ah, sb + ZS_OFF + aa);
#pragma unroll
                for (int nt = 0; nt < 2; ++nt)
                    mma_f16(acc[mt][nt], ah, bh[nt]);
            }
        }

        // epilogue: float2 stores
#pragma unroll
        for (int nt = 0; nt < 2; ++nt) {
            const long long n = (long long)strip * 128 + wn * 16 + nt * 8 + 2 * (lane & 3);
            const float2 bd = *(const float2*)(bdec + n);
#pragma unroll
            for (int mt = 0; mt < 2; ++mt) {
                const int b = wm * 32 + mt * 16 + (lane >> 2);
                float2 v0, v1;
                v0.x = acc[mt][nt][0] + bd.x;  v0.y = acc[mt][nt][1] + bd.y;
                v1.x = acc[mt][nt][2] + bd.x;  v1.y = acc[mt][nt][3] + bd.y;
                *(float2*)(out_loc + (long long)b * NTOT + n)       = v0;
                *(float2*)(out_loc + (long long)(b + 8) * NTOT + n) = v1;
            }
        }

        stage ^= 1;
    }
}

// ---------------------------------------------------------------------------
// Launch
// ---------------------------------------------------------------------------
extern "C" void kernel_launch(void* const* d_in, const int* in_sizes, int n_in,
                              void* d_out, int out_size) {
    const float* x          = (const float*)d_in[0];
    const int*   label      = (const int*)d_in[1];
    const float* actionbias = (const float*)d_in[2];
    const float* W_mu       = (const float*)d_in[3];
    const float* b_mu       = (const float*)d_in[4];
    const float* W_std      = (const float*)d_in[5];
    const float* b_std      = (const float*)d_in[6];
    const float* W_dec      = (const float*)d_in[7];
    const float* b_dec      = (const float*)d_in[8];
    const float* log_scale  = (const float*)d_in[9];
    float* out = (float*)d_out;

    static int smem_set = 0;
    if (!smem_set) {
        cudaFuncSetAttribute(k3_decoder_mma, cudaFuncAttributeMaxDynamicSharedMemorySize,
                             K3_SMEM);
        smem_set = 1;
    }

    dim3 g1(NB, NSEG);
    k1_pool<<<g1, 256>>>(x);
    k2_encode<<<NB + 1, 512>>>(W_mu, b_mu, W_std, b_std, actionbias, label, log_scale, out);
    k3_decoder_mma<<<K3_GRID, 512, K3_SMEM>>>(W_dec, b_dec, out + OFF_LOC);
}

// round 15
// speedup vs baseline: 1.0957x; 1.0487x over previous
#include <cuda_runtime.h>
#include <cuda_bf16.h>
#include <cuda_fp16.h>
#include <cstdint>

// ---------------------------------------------------------------------------
// Problem constants
// ---------------------------------------------------------------------------
#define NB 64
#define NT 512
#define NF 1024
#define NL 128
#define NTOT (NT * NF)          // 524288 = T*F
#define NSEG 8                  // t-segments per batch in K1 (512 blocks = 1 wave)

// Output layout (flat concat in reference return order)
#define OFF_MU    0
#define OFF_STD   (NB * NL)                 // 8192
#define OFF_ZS    (2 * NB * NL)             // 16384
#define OFF_LOC   (3 * NB * NL)             // 24576
#define OFF_SCALE (3 * NB * NL + NB * NTOT) // 33579008

// ---------------------------------------------------------------------------
// Device scratch (no allocation allowed)
// ---------------------------------------------------------------------------
__device__ float g_hpart[NB * NSEG * NF];   // partial sums
__device__ float g_cntpart[NB * NSEG];      // partial mask counts
__device__ float g_zs[NB * NL];             // zs for decoder

// ---------------------------------------------------------------------------
// Small helpers
// ---------------------------------------------------------------------------
__device__ __forceinline__ float softplus_f(float v) {
    return fmaxf(v, 0.0f) + log1pf(expf(-fabsf(v)));
}

// Threefry-2x32, 20 rounds — exact JAX key schedule
__device__ __forceinline__ void tf2x32(unsigned int k0, unsigned int k1,
                                       unsigned int x0, unsigned int x1,
                                       unsigned int& o0, unsigned int& o1) {
    unsigned int ks2 = k0 ^ k1 ^ 0x1BD11BDAu;
    x0 += k0; x1 += k1;
#define TF_R(r) { x0 += x1; x1 = (x1 << (r)) | (x1 >> (32 - (r))); x1 ^= x0; }
    TF_R(13) TF_R(15) TF_R(26) TF_R(6)
    x0 += k1;  x1 += ks2 + 1u;
    TF_R(17) TF_R(29) TF_R(16) TF_R(24)
    x0 += ks2; x1 += k0 + 2u;
    TF_R(13) TF_R(15) TF_R(26) TF_R(6)
    x0 += k0;  x1 += k1 + 3u;
    TF_R(17) TF_R(29) TF_R(16) TF_R(24)
    x0 += k1;  x1 += ks2 + 4u;
    TF_R(13) TF_R(15) TF_R(26) TF_R(6)
    x0 += ks2; x1 += k0 + 5u;
#undef TF_R
    o0 = x0; o1 = x1;
}

// XLA f32 erf_inv (Giles polynomial)
__device__ __forceinline__ float erfinv_xla(float x) {
    float w = -log1pf(-x * x);
    float p;
    if (w < 5.0f) {
        w = w - 2.5f;
        p = 2.81022636e-08f;
        p = fmaf(p, w, 3.43273939e-07f);
        p = fmaf(p, w, -3.5233877e-06f);
        p = fmaf(p, w, -4.39150654e-06f);
        p = fmaf(p, w, 0.00021858087f);
        p = fmaf(p, w, -0.00125372503f);
        p = fmaf(p, w, -0.00417768164f);
        p = fmaf(p, w, 0.246640727f);
        p = fmaf(p, w, 1.50140941f);
    } else {
        w = sqrtf(w) - 3.0f;
        p = -0.000200214257f;
        p = fmaf(p, w, 0.000100950558f);
        p = fmaf(p, w, 0.00134934322f);
        p = fmaf(p, w, -0.00367342844f);
        p = fmaf(p, w, 0.00573950773f);
        p = fmaf(p, w, -0.0076224613f);
        p = fmaf(p, w, 0.00943887047f);
        p = fmaf(p, w, 1.00167406f);
        p = fmaf(p, w, 2.83297682f);
    }
    return p * x;
}

// ---------------------------------------------------------------------------
// mma.sync / ldmatrix / cp.async helpers (portable sm_80+ PTX)
// ---------------------------------------------------------------------------
__device__ __forceinline__ uint32_t smem_to_u32(const void* smem_ptr) {
    uint32_t addr;
    asm("{ .reg .u64 tmp; cvta.to.shared.u64 tmp, %1; cvt.u32.u64 %0, tmp; }"
        : "=r"(addr) : "l"(smem_ptr));
    return addr;
}

__device__ __forceinline__ void ldsm_x4(uint32_t* r, uint32_t addr) {
    asm volatile("ldmatrix.sync.aligned.m8n8.x4.shared.b16 {%0,%1,%2,%3}, [%4];"
        : "=r"(r[0]), "=r"(r[1]), "=r"(r[2]), "=r"(r[3]) : "r"(addr));
}

__device__ __forceinline__ void ldsm_x2_trans(uint32_t* r, uint32_t addr) {
    asm volatile("ldmatrix.sync.aligned.m8n8.x2.trans.shared.b16 {%0,%1}, [%2];"
        : "=r"(r[0]), "=r"(r[1]) : "r"(addr));
}

__device__ __forceinline__ void mma_f16(float* d, const uint32_t* a, const uint32_t* b) {
    asm volatile(
        "mma.sync.aligned.m16n8k16.row.col.f32.f16.f16.f32 "
        "{%0,%1,%2,%3}, {%4,%5,%6,%7}, {%8,%9}, {%0,%1,%2,%3};"
        : "+f"(d[0]), "+f"(d[1]), "+f"(d[2]), "+f"(d[3])
        : "r"(a[0]), "r"(a[1]), "r"(a[2]), "r"(a[3]), "r"(b[0]), "r"(b[1]));
}

__device__ __forceinline__ uint32_t pack_h2(float x, float y) {
    __half2 h = __floats2half2_rn(x, y);
    return *(uint32_t*)&h;
}

__device__ __forceinline__ void cp_async16(uint32_t dst_smem, const void* src_gmem) {
    asm volatile("cp.async.cg.shared.global [%0], [%1], 16;"
                 :: "r"(dst_smem), "l"(src_gmem));
}
#define CP_COMMIT() asm volatile("cp.async.commit_group;" ::: "memory")
#define CP_WAIT1()  asm volatile("cp.async.wait_group 1;" ::: "memory")

// streaming (evict-first) 8B store — loc is never re-read
__device__ __forceinline__ void stg_cs_f2(float* p, float2 v) {
    asm volatile("st.global.cs.v2.f32 [%0], {%1, %2};"
                 :: "l"(p), "f"(v.x), "f"(v.y) : "memory");
}

// ---------------------------------------------------------------------------
// K1: column-sum over t (mask only affects the count).  grid (NB, NSEG=8)
// = 512 blocks -> single wave at 4 CTAs/SM (no wave tail).
// ---------------------------------------------------------------------------
__global__ __launch_bounds__(256, 4) void k1_pool(const float* __restrict__ x) {
    const int b = blockIdx.x;
    const int s = blockIdx.y;
    const int warp = threadIdx.x >> 5;
    const int lane = threadIdx.x & 31;

    __shared__ float hsh[NF];
    __shared__ int cnt_sh;
    for (int i = threadIdx.x; i < NF; i += 256) hsh[i] = 0.0f;
    if (threadIdx.x == 0) cnt_sh = 0;
    __syncthreads();

    float4 acc[8];
#pragma unroll
    for (int j = 0; j < 8; ++j) acc[j] = make_float4(0.f, 0.f, 0.f, 0.f);
    int cnt = 0;

    const float* xb = x + ((long long)b * NT + s * (NT / NSEG)) * NF;
    const int rows = NT / NSEG;  // 64
    for (int r = warp; r < rows; r += 8) {
        const float4* row4 = (const float4*)(xb + (long long)r * NF);
        float sum = 0.0f;
#pragma unroll
        for (int j = 0; j < 8; ++j) {
            const float4 v = row4[lane + 32 * j];
            acc[j].x += v.x; acc[j].y += v.y;
            acc[j].z += v.z; acc[j].w += v.w;
            sum += (v.x + v.y) + (v.z + v.w);
        }
#pragma unroll
        for (int o = 16; o > 0; o >>= 1) sum += __shfl_xor_sync(0xffffffffu, sum, o);
        if (sum != 0.0f) cnt++;
    }

#pragma unroll
    for (int j = 0; j < 8; ++j) {
        const int base = (lane + 32 * j) * 4;
        atomicAdd(&hsh[base + 0], acc[j].x);
        atomicAdd(&hsh[base + 1], acc[j].y);
        atomicAdd(&hsh[base + 2], acc[j].z);
        atomicAdd(&hsh[base + 3], acc[j].w);
    }
    if (lane == 0) atomicAdd(&cnt_sh, cnt);
    __syncthreads();

    const int part = b * NSEG + s;
    for (int i = threadIdx.x; i < NF; i += 256) g_hpart[part * NF + i] = hsh[i];
    if (threadIdx.x == 0) g_cntpart[part] = (float)cnt_sh;
}

// ---------------------------------------------------------------------------
// K2: encoder heads + threefry eps + zs.  grid NB+1, 512 threads.
// Extra block writes scale = softplus(log_scale).
// ---------------------------------------------------------------------------
__global__ __launch_bounds__(512) void k2_encode(
    const float* __restrict__ Wmu, const float* __restrict__ bmu,
    const float* __restrict__ Wstd, const float* __restrict__ bstd,
    const float* __restrict__ actionbias, const int* __restrict__ label,
    const float* __restrict__ log_scale,
    float* __restrict__ out) {
    if (blockIdx.x == NB) {
        for (int f = threadIdx.x; f < NF; f += 512)
            out[OFF_SCALE + f] = softplus_f(log_scale[f]);
        return;
    }
    const int b = blockIdx.x;
    const int l = threadIdx.x & 127;
    const int q = threadIdx.x >> 7;   // 0..3

    __shared__ float hsh[NF];
    __shared__ float red_mu[4][NL];
    __shared__ float red_sp[4][NL];
    __shared__ float inv_denom;

    for (int f = threadIdx.x; f < NF; f += 512) {
        float sum = 0.0f;
#pragma unroll
        for (int p = 0; p < NSEG; ++p) sum += g_hpart[(b * NSEG + p) * NF + f];
        hsh[f] = sum;
    }
    if (threadIdx.x == 0) {
        float c = 0.0f;
#pragma unroll
        for (int p = 0; p < NSEG; ++p) c += g_cntpart[b * NSEG + p];
        inv_denom = 1.0f / fmaxf(c, 1.0f);
    }
    __syncthreads();
    const float inv = inv_denom;
    for (int f = threadIdx.x; f < NF; f += 512) hsh[f] *= inv;
    __syncthreads();

    float mu = 0.0f;
    float sp = 0.0f;
    const int f0 = q * (NF / 4);
#pragma unroll 8
    for (int f = f0; f < f0 + NF / 4; ++f) {
        const float hv = hsh[f];
        mu = fmaf(hv, Wmu[f * NL + l], mu);
        sp = fmaf(hv, Wstd[f * NL + l], sp);
    }
    red_mu[q][l] = mu;
    red_sp[q][l] = sp;
    __syncthreads();

    if (q == 0) {
        mu = ((red_mu[0][l] + red_mu[1][l]) + (red_mu[2][l] + red_mu[3][l])) + bmu[l];
        sp = ((red_sp[0][l] + red_sp[1][l]) + (red_sp[2][l] + red_sp[3][l])) + bstd[l];
        const float stdv = softplus_f(sp);

        unsigned int nk0, nk1;
        tf2x32(0u, 0u, 0u, 1u, nk0, nk1);
        const int idx = b * NL + l;
        unsigned int o0, o1;
        tf2x32(nk0, nk1, 0u, (unsigned int)idx, o0, o1);
        const unsigned int bits = o0 ^ o1;
        const float f01 = __uint_as_float(0x3F800000u | (bits >> 9)) - 1.0f;
        float u = fmaf(f01, 2.0f, -0.99999994f);
        u = fmaxf(u, -0.99999994f);
        const float eps = 1.41421356237309515f * erfinv_xla(u);

        const float zs = mu + stdv * eps + actionbias[label[b] * NL + l];

        out[OFF_MU + idx]  = mu;
        out[OFF_STD + idx] = stdv;
        out[OFF_ZS + idx]  = zs;
        g_zs[idx] = zs;
    }
}

// ---------------------------------------------------------------------------
// K3: decoder GEMM, fp16 single-pass mma.sync, wide-strip cp.async pipeline.
// Strip = 64 b x 128 n x K=128 (512B bursts). 1 CTA/SM (grid 148), 512 thr.
// 2-stage 64KB f32 ring; convert -> fp16 buffer -> ldsm/mma.
// Epilogue uses st.global.cs (loc is write-once, keep it out of L2).
// ---------------------------------------------------------------------------
#define K3_GRID   148
#define K3_STRIPS (NTOT / 128)   // 4096
#define ROWB   272               // zs fp16 row stride (64 rows)
#define WROWB  272               // W fp16 row stride (128 fp16 = 256B + 16 pad)
#define F32ROW 512               // W f32 row stride (128 f32, contiguous)

#define ZS_OFF  0
#define WH_OFF  (64 * ROWB)                      // 17408
#define F32_OFF (WH_OFF + 128 * WROWB)           // 52224
#define F32_STAGE (128 * F32ROW)                 // 65536
#define K3_SMEM (F32_OFF + 2 * F32_STAGE)        // 183296

__global__ __launch_bounds__(512, 1) void k3_decoder_mma(const float* __restrict__ Wd,
                                                         const float* __restrict__ bdec,
                                                         float* __restrict__ out_loc) {
    extern __shared__ char smem[];
    const uint32_t sb = smem_to_u32(smem);
    const int tid  = threadIdx.x;
    const int wid  = tid >> 5;
    const int lane = tid & 31;
    const int wm   = wid & 1;         // M half (b 0-31 / 32-63)
    const int wn   = wid >> 1;        // n group of 16 (0..7)
    const int tl0  = tid >> 5;        // convert: base l row (0..15)

    // --- prologue: zs fp16 into smem [b][l] (built once) ---
    for (int i = tid; i < NB * NL; i += 512) {
        const int b = i >> 7;
        const int l = i & 127;
        *(__half*)(smem + ZS_OFF + b * ROWB + l * 2) = __float2half_rn(__ldg(&g_zs[i]));
    }

    // issue cp.async for one W strip (128 rows x 512B) into ring stage s
#define K3_ISSUE(strip_, s_) do { \
        const uint32_t _dst = sb + F32_OFF + (s_) * F32_STAGE; \
        const float* _src = Wd + (long long)(strip_) * 128; \
        _Pragma("unroll") \
        for (int k = 0; k < 8; ++k) { \
            const int _idx = tid + k * 512; \
            const int _row = _idx >> 5; \
            const int _c   = _idx & 31; \
            cp_async16(_dst + _row * F32ROW + _c * 16, \
                       _src + (long long)_row * NTOT + _c * 4); \
        } \
    } while (0)

    // convert ring stage s (f32) -> fp16 W buffer; warp = one row (conflict-free)
#define K3_CONVERT(s_) do { \
        const char* _f32 = smem + F32_OFF + (s_) * F32_STAGE; \
        _Pragma("unroll") \
        for (int p = 0; p < 8; ++p) { \
            const int l = tl0 + p * 16; \
            const float4 v = *(const float4*)(_f32 + l * F32ROW + lane * 16); \
            uint2 h; \
            h.x = pack_h2(v.x, v.y); \
            h.y = pack_h2(v.z, v.w); \
            *(uint2*)(smem + WH_OFF + l * WROWB + lane * 8) = h; \
        } \
    } while (0)

    int strip = blockIdx.x;
    K3_ISSUE(strip, 0);
    CP_COMMIT();
    int stage = 0;

    // A fragment base: rows wm*32 + (lane&15), col-halves by lane>>4
    const uint32_t arow = (uint32_t)(wm * 32 + (lane & 15)) * ROWB + (uint32_t)(lane >> 4) * 16;
    // B fragment base: rows (lane&15) of k-dim, n offset = wn*16 fp16 = 32B
    const uint32_t brow = (uint32_t)(lane & 15) * WROWB + (uint32_t)wn * 32;

    for (; strip < K3_STRIPS; strip += K3_GRID) {
        const int next = strip + K3_GRID;
        if (next < K3_STRIPS) K3_ISSUE(next, stage ^ 1);
        CP_COMMIT();
        CP_WAIT1();            // current strip's stage resident
        __syncthreads();       // orders prior mma reads vs convert writes

        K3_CONVERT(stage);
        __syncthreads();

        float acc[2][2][4];
#pragma unroll
        for (int mt = 0; mt < 2; ++mt)
#pragma unroll
            for (int nt = 0; nt < 2; ++nt)
#pragma unroll
                for (int r = 0; r < 4; ++r) acc[mt][nt][r] = 0.0f;

#pragma unroll
        for (int ks = 0; ks < 8; ++ks) {
            uint32_t bh[2][2];
            const uint32_t bb = (uint32_t)(16 * ks) * WROWB + brow;
            ldsm_x2_trans(bh[0], sb + WH_OFF + bb);
            ldsm_x2_trans(bh[1], sb + WH_OFF + bb + 16);
#pragma unroll
            for (int mt = 0; mt < 2; ++mt) {
                uint32_t ah[4];
                const uint32_t aa = (uint32_t)(16 * mt) * ROWB + arow + (uint32_t)(ks * 32);
                ldsm_x4(ah, sb + ZS_OFF + aa);
#pragma unroll
                for (int nt = 0; nt < 2; ++nt)
                    mma_f16(acc[mt][nt], ah, bh[nt]);
            }
        }

        // epilogue: streaming float2 stores (evict-first)
#pragma unroll
        for (int nt = 0; nt < 2; ++nt) {
            const long long n = (long long)strip * 128 + wn * 16 + nt * 8 + 2 * (lane & 3);
            const float2 bd = *(const float2*)(bdec + n);
#pragma unroll
            for (int mt = 0; mt < 2; ++mt) {
                const int b = wm * 32 + mt * 16 + (lane >> 2);
                float2 v0, v1;
                v0.x = acc[mt][nt][0] + bd.x;  v0.y = acc[mt][nt][1] + bd.y;
                v1.x = acc[mt][nt][2] + bd.x;  v1.y = acc[mt][nt][3] + bd.y;
                stg_cs_f2(out_loc + (long long)b * NTOT + n, v0);
                stg_cs_f2(out_loc + (long long)(b + 8) * NTOT + n, v1);
            }
        }

        stage ^= 1;
    }
}

// ---------------------------------------------------------------------------
// Launch
// ---------------------------------------------------------------------------
extern "C" void kernel_launch(void* const* d_in, const int* in_sizes, int n_in,
                              void* d_out, int out_size) {
    const float* x          = (const float*)d_in[0];
    const int*   label      = (const int*)d_in[1];
    const float* actionbias = (const float*)d_in[2];
    const float* W_mu       = (const float*)d_in[3];
    const float* b_mu       = (const float*)d_in[4];
    const float* W_std      = (const float*)d_in[5];
    const float* b_std      = (const float*)d_in[6];
    const float* W_dec      = (const float*)d_in[7];
    const float* b_dec      = (const float*)d_in[8];
    const float* log_scale  = (const float*)d_in[9];
    float* out = (float*)d_out;

    static int smem_set = 0;
    if (!smem_set) {
        cudaFuncSetAttribute(k3_decoder_mma, cudaFuncAttributeMaxDynamicSharedMemorySize,
                             K3_SMEM);
        smem_set = 1;
    }

    dim3 g1(NB, NSEG);
    k1_pool<<<g1, 256>>>(x);
    k2_encode<<<NB + 1, 512>>>(W_mu, b_mu, W_std, b_std, actionbias, label, log_scale, out);
    k3_decoder_mma<<<K3_GRID, 512, K3_SMEM>>>(W_dec, b_dec, out + OFF_LOC);
}